// round 5
// baseline (speedup 1.0000x reference)
#include <cuda_runtime.h>
#include <math.h>

#define NN 256
#define MM 1024
#define CC 64
#define KK 16

__device__ float g_xyz[NN*3];
__device__ float g_rf[MM*CC];
__device__ float g_rfi[MM*3];
__device__ float g_wpn[NN*CC];
__device__ float g_rfn[MM*CC];
__device__ float g_sim1[MM*NN];
__device__ float g_sim2[MM*NN];
__device__ float g_invc1[NN], g_invr1[MM], g_invc2[NN], g_invr2[MM];
__device__ int   g_knn[NN*KK];
__device__ float g_pcf[NN*CC];
__device__ float g_imgf[MM*CC];
__device__ float g_pcn[NN*CC];
__device__ float g_imgn[MM*CC];
__device__ float4 g_simQ[NN*MM];
__device__ float g_basem[MM*128];
__device__ float g_basen[NN*128];
__device__ float g_att[NN*CC];
__device__ float g_corres[NN*3];
__device__ float g_win[NN];

__global__ void prep_kernel(const float* __restrict__ wx, const float* __restrict__ lz,
                            const float* __restrict__ RF3, const float* __restrict__ RF3i){
  int m=blockIdx.x, t=threadIdx.x;
  g_rf[m*CC+t]=RF3[t*MM+m];
  if(t<3) g_rfi[m*3+t]=RF3i[t*MM+m];
  if(m<NN&&t<3) g_xyz[m*3+t]=wx[m*3+t]*lz[m];
}

__global__ void l2norm_kernel(const float* __restrict__ ext,int sel){
  const float* src; float* dst;
  if(sel==0){src=ext;dst=g_wpn;} else if(sel==1){src=g_rf;dst=g_rfn;}
  else if(sel==2){src=g_pcf;dst=g_pcn;} else {src=g_imgf;dst=g_imgn;}
  int r=blockIdx.x,t=threadIdx.x;
  float v=src[r*CC+t], s=v*v;
  for(int o=16;o;o>>=1) s+=__shfl_down_sync(~0u,s,o);
  __shared__ float sh[2];
  if((t&31)==0) sh[t>>5]=s;
  __syncthreads();
  float n=fmaxf(sqrtf(sh[0]+sh[1]),1e-12f);
  dst[r*CC+t]=v/n;
}

__global__ __launch_bounds__(256) void corr_kernel(int sel){
  const float *A,*B; float* S;
  if(sel==0){A=g_rfn;B=g_wpn;S=g_sim1;} else {A=g_imgn;B=g_pcn;S=g_sim2;}
  __shared__ float As[64][65], Bs[64][65];
  int t=threadIdx.x, tx=t&15, ty=t>>4;
  int m0=blockIdx.x*64, n0=blockIdx.y*64;
  #pragma unroll
  for(int i=0;i<16;i++){int idx=t+i*256,r=idx>>6,c=idx&63;
    As[r][c]=A[(m0+r)*CC+c]; Bs[r][c]=B[(n0+r)*CC+c];}
  __syncthreads();
  float acc[4][4];
  #pragma unroll
  for(int i=0;i<4;i++)
    #pragma unroll
    for(int j=0;j<4;j++) acc[i][j]=0.f;
  #pragma unroll 8
  for(int k=0;k<64;k++){
    float a[4],b[4];
    #pragma unroll
    for(int i=0;i<4;i++){a[i]=As[ty*4+i][k]; b[i]=Bs[tx*4+i][k];}
    #pragma unroll
    for(int i=0;i<4;i++)
      #pragma unroll
      for(int j=0;j<4;j++) acc[i][j]+=a[i]*b[j];
  }
  #pragma unroll
  for(int i=0;i<4;i++)
    #pragma unroll
    for(int j=0;j<4;j++) S[(m0+ty*4+i)*NN+n0+tx*4+j]=acc[i][j];
}

__global__ void colmax_kernel(int sel){
  const float* S=sel?g_sim2:g_sim1; float* ic=sel?g_invc2:g_invc1;
  int n=threadIdx.x; float mx=-1e30f;
  for(int m=0;m<MM;m++) mx=fmaxf(mx,S[m*NN+n]);
  ic[n]=1.f/(mx+1e-6f);
}
__global__ void rowmax_kernel(int sel){
  const float* S=sel?g_sim2:g_sim1; float* ir=sel?g_invr2:g_invr1;
  int w=threadIdx.x>>5,l=threadIdx.x&31,m=blockIdx.x*8+w;
  float mx=-1e30f;
  for(int n=l;n<NN;n+=32) mx=fmaxf(mx,S[m*NN+n]);
  for(int o=16;o;o>>=1) mx=fmaxf(mx,__shfl_down_sync(~0u,mx,o));
  if(l==0) ir[m]=1.f/(mx+1e-10f);
}

__global__ void knn_kernel(){
  int n=blockIdx.x,t=threadIdx.x;
  __shared__ float sx[NN*3], d2[NN], wm[8];
  __shared__ int wi[8];
  for(int i=t;i<NN*3;i+=256) sx[i]=g_xyz[i];
  __syncthreads();
  float cx=sx[n*3],cy=sx[n*3+1],cz=sx[n*3+2];
  float dx=sx[t*3]-cx,dy=sx[t*3+1]-cy,dz=sx[t*3+2]-cz;
  d2[t]=dx*dx+dy*dy+dz*dz;
  __syncthreads();
  for(int it=0;it<KK;it++){
    float v=d2[t]; int id=t;
    for(int o=16;o;o>>=1){
      float ov=__shfl_down_sync(~0u,v,o); int oi=__shfl_down_sync(~0u,id,o);
      if(ov<v||(ov==v&&oi<id)){v=ov;id=oi;}
    }
    if((t&31)==0){wm[t>>5]=v;wi[t>>5]=id;}
    __syncthreads();
    if(t==0){
      float bv=wm[0];int bi=wi[0];
      for(int w=1;w<8;w++) if(wm[w]<bv||(wm[w]==bv&&wi[w]<bi)){bv=wm[w];bi=wi[w];}
      g_knn[n*KK+it]=bi; d2[bi]=1e38f;
    }
    __syncthreads();
  }
}

#define MLP2_SMEM (15888*4)
__global__ __launch_bounds__(256) void mlp2_kernel(const float* __restrict__ wp,
    const float* __restrict__ w0,const float* __restrict__ b0,
    const float* __restrict__ w1,const float* __restrict__ b1,
    const float* __restrict__ w2,const float* __restrict__ b2){
  extern __shared__ float sm[];
  float* W0=sm; float* W1=W0+4352; float* W2=W1+4096;
  float* B0=W2+4096; float* B1=B0+64; float* B2=B1+64;
  float* IN=B2+64; float* Ha=IN+1088; float* Hb=Ha+1024; float* wk=Hb+1024;
  int n=blockIdx.x,t=threadIdx.x;
  for(int i=t;i<4352;i+=256) W0[i]=w0[i];
  for(int i=t;i<4096;i+=256){W1[i]=w1[i];W2[i]=w2[i];}
  if(t<64){B0[t]=b0[t];B1[t]=b1[t];B2[t]=b2[t];}
  for(int i=t;i<16*68;i+=256){
    int k=i/68,f=i%68,nb=g_knn[n*KK+k]; float val;
    if(f<64) val=wp[nb*CC+f];
    else if(f<67) val=g_xyz[nb*3+(f-64)]-g_xyz[n*3+(f-64)];
    else{
      float dx=g_xyz[nb*3]-g_xyz[n*3],dy=g_xyz[nb*3+1]-g_xyz[n*3+1],dz=g_xyz[nb*3+2]-g_xyz[n*3+2];
      val=sqrtf(dx*dx+dy*dy+dz*dz);
    }
    IN[k*68+f]=val;
  }
  __syncthreads();
  for(int o=t;o<1024;o+=256){int k=o>>6,j=o&63; float s=B0[j];
    #pragma unroll 4
    for(int i=0;i<68;i++) s+=IN[k*68+i]*W0[i*64+j];
    Ha[o]=fmaxf(s,0.f);}
  __syncthreads();
  for(int o=t;o<1024;o+=256){int k=o>>6,j=o&63; float s=B1[j];
    #pragma unroll 4
    for(int i=0;i<64;i++) s+=Ha[k*64+i]*W1[i*64+j];
    Hb[o]=fmaxf(s,0.f);}
  __syncthreads();
  for(int o=t;o<1024;o+=256){int k=o>>6,j=o&63; float s=B2[j];
    #pragma unroll 4
    for(int i=0;i<64;i++) s+=Hb[k*64+i]*W2[i*64+j];
    Ha[o]=fmaxf(s,0.f);}
  __syncthreads();
  if(t<16){float mx=-1e30f; for(int j=0;j<64;j++) mx=fmaxf(mx,Ha[t*64+j]); wk[t]=mx;}
  __syncthreads();
  if(t==0){
    float mx=-1e30f; for(int k=0;k<16;k++) mx=fmaxf(mx,wk[k]);
    float s=0.f; for(int k=0;k<16;k++){wk[k]=expf(wk[k]-mx);s+=wk[k];}
    float inv=1.f/s; for(int k=0;k<16;k++) wk[k]*=inv;
  }
  __syncthreads();
  if(t<64){float s=0.f; for(int k=0;k<16;k++) s+=wk[k]*IN[k*68+t]; g_pcf[n*CC+t]=s;}
}

#define MLP3_SMEM (14443*4)
__global__ __launch_bounds__(256) void mlp3_kernel(
    const float* __restrict__ w0,const float* __restrict__ b0,
    const float* __restrict__ w1,const float* __restrict__ b1,
    const float* __restrict__ w2,const float* __restrict__ b2){
  extern __shared__ float sm[];
  float* W0=sm; float* W1=W0+4288; float* W2=W1+4096;
  float* B0=W2+4096; float* B1=B0+64; float* B2=B1+64;
  float* IN=B2+64; float* Ha=IN+603; float* Hb=Ha+576; float* wk=Hb+576;
  int m=blockIdx.x,t=threadIdx.x,y=m>>5,x=m&31;
  for(int i=t;i<4288;i+=256) W0[i]=w0[i];
  for(int i=t;i<4096;i+=256){W1[i]=w1[i];W2[i]=w2[i];}
  if(t<64){B0[t]=b0[t];B1[t]=b1[t];B2[t]=b2[t];}
  for(int i=t;i<9*67;i+=256){
    int k=i/67,f=i%67,dy=k/3-1,dx=k%3-1,yy=y+dy,xx=x+dx;
    float val=0.f;
    if(yy>=0&&yy<32&&xx>=0&&xx<32){int mm=yy*32+xx; val=(f<3)?g_rfi[mm*3+f]:g_rf[mm*CC+f-3];}
    IN[k*67+f]=val;
  }
  __syncthreads();
  for(int o=t;o<576;o+=256){int k=o>>6,j=o&63; float s=B0[j];
    #pragma unroll 4
    for(int i=0;i<67;i++) s+=IN[k*67+i]*W0[i*64+j];
    Ha[o]=fmaxf(s,0.f);}
  __syncthreads();
  for(int o=t;o<576;o+=256){int k=o>>6,j=o&63; float s=B1[j];
    #pragma unroll 4
    for(int i=0;i<64;i++) s+=Ha[k*64+i]*W1[i*64+j];
    Hb[o]=fmaxf(s,0.f);}
  __syncthreads();
  for(int o=t;o<576;o+=256){int k=o>>6,j=o&63; float s=B2[j];
    #pragma unroll 4
    for(int i=0;i<64;i++) s+=Hb[k*64+i]*W2[i*64+j];
    Ha[o]=fmaxf(s,0.f);}
  __syncthreads();
  if(t<9){float mx=-1e30f; for(int j=0;j<64;j++) mx=fmaxf(mx,Ha[t*64+j]); wk[t]=mx;}
  __syncthreads();
  if(t==0){
    float mx=-1e30f; for(int k=0;k<9;k++) mx=fmaxf(mx,wk[k]);
    float s=0.f; for(int k=0;k<9;k++){wk[k]=expf(wk[k]-mx);s+=wk[k];}
    float inv=1.f/s; for(int k=0;k<9;k++) wk[k]*=inv;
  }
  __syncthreads();
  if(t<64){float s=0.f; for(int k=0;k<9;k++) s+=wk[k]*IN[k*67+3+t]; g_imgf[m*CC+t]=s;}
}

__global__ void pack_kernel(){
  int n=blockIdx.x,t=threadIdx.x;
  float ic1=g_invc1[n],ic2=g_invc2[n];
  for(int m=t;m<MM;m+=256){
    float s1=g_sim1[m*NN+n],s2=g_sim2[m*NN+n];
    float4 q; q.x=s1*ic1; q.y=s1*g_invr1[m]; q.z=s2*ic2; q.w=s2*g_invr2[m];
    g_simQ[n*MM+m]=q;
  }
}

__global__ void basem_kernel(const float* __restrict__ w1_0,const float* __restrict__ b1_0){
  int m=blockIdx.x,t=threadIdx.x;
  __shared__ float in[67];
  if(t<3) in[t]=g_rfi[m*3+t]; else if(t<67) in[t]=g_rf[m*CC+t-3];
  __syncthreads();
  float acc=b1_0[t];
  #pragma unroll
  for(int i=0;i<3;i++) acc+=in[i]*w1_0[(3+i)*128+t];
  #pragma unroll 4
  for(int i=0;i<64;i++) acc+=in[3+i]*w1_0[(70+i)*128+t];
  g_basem[m*128+t]=acc;
}
__global__ void basen_kernel(const float* __restrict__ wp,const float* __restrict__ w1_0){
  int n=blockIdx.x,t=threadIdx.x;
  __shared__ float in[67];
  if(t<3) in[t]=g_xyz[n*3+t]; else if(t<67) in[t]=wp[n*CC+t-3];
  __syncthreads();
  float acc=0.f;
  #pragma unroll
  for(int i=0;i<3;i++) acc+=in[i]*w1_0[i*128+t];
  #pragma unroll 4
  for(int i=0;i<64;i++) acc+=in[3+i]*w1_0[(6+i)*128+t];
  g_basen[n*128+t]=acc;
}

#define OWS 0
#define OWA 512
#define OWB 8704
#define OBA 12800
#define OBB 12864
#define OBN 12928
#define OBM 13184
#define OH1 21440
#define OH2 29696
#define OF  34048
#define ORM 38400
#define OEE 38464
#define OAS 38528
#define OCO 38656
#define OZS 38664
#define OMS 38666
#define OAL 38668
#define BIG_SMEM (38672*4)

__global__ __launch_bounds__(256,1) void big_kernel(
    const float* __restrict__ w1_0,const float* __restrict__ w1_1,const float* __restrict__ b1_1,
    const float* __restrict__ w1_2,const float* __restrict__ b1_2){
  extern __shared__ float sm[];
  float* WS=sm+OWS; float* WA=sm+OWA; float* WB=sm+OWB;
  float* BA=sm+OBA; float* BB=sm+OBB; float* BN=sm+OBN; float* Bm=sm+OBM;
  float* H1=sm+OH1; float* H2=sm+OH2; float* F=sm+OF;
  float* RM=sm+ORM; float* EE=sm+OEE; float* AS=sm+OAS; float* CO=sm+OCO;
  float* ZS=sm+OZS; float* MS=sm+OMS; float* AL=sm+OAL;
  int t=threadIdx.x, n0=blockIdx.x*2;
  for(int i=t;i<512;i+=256) WS[i]=w1_0[134*128+i];
  for(int i=t;i<8192;i+=256) WA[i]=w1_1[i];
  for(int i=t;i<4096;i+=256) WB[i]=w1_2[i];
  if(t<64){BA[t]=b1_1[t];BB[t]=b1_2[t];}
  BN[t]=g_basen[n0*128+t];
  if(t<128) AS[t]=0.f;
  if(t<8) CO[t]=0.f;
  if(t==0){ZS[0]=ZS[1]=0.f; MS[0]=MS[1]=-1e30f;}
  __syncthreads();
  int tx=t&15, ty=t>>4, mloc=t&63, q=t>>6;
  for(int tile=0;tile<16;tile++){
    for(int idx=t;idx<64*128;idx+=256){int mr=idx>>7,c=idx&127; Bm[mr*129+c]=g_basem[(tile*64+mr)*128+c];}
    __syncthreads();
    for(int p=0;p<2;p++){
      int n=n0+p;
      { // phase A: H1 = relu(basen + basem + sim4@WS)
        float4 s4=g_simQ[n*MM+tile*64+mloc];
        const float* bn=BN+p*128;
        #pragma unroll 8
        for(int ci=0;ci<32;ci++){
          int c=q*32+ci;
          float h=bn[c]+Bm[mloc*129+c]+s4.x*WS[c]+s4.y*WS[128+c]+s4.z*WS[256+c]+s4.w*WS[384+c];
          H1[mloc*129+c]=fmaxf(h,0.f);
        }
      }
      __syncthreads();
      { // phase B: H2 = relu(H1 @ W1_1 + b)
        float acc[4][4];
        #pragma unroll
        for(int i=0;i<4;i++)
          #pragma unroll
          for(int j=0;j<4;j++) acc[i][j]=BA[tx*4+j];
        #pragma unroll 4
        for(int k=0;k<128;k++){
          float a0=H1[(ty*4+0)*129+k],a1=H1[(ty*4+1)*129+k],a2=H1[(ty*4+2)*129+k],a3=H1[(ty*4+3)*129+k];
          float4 bv=*(const float4*)&WA[k*64+tx*4];
          acc[0][0]+=a0*bv.x;acc[0][1]+=a0*bv.y;acc[0][2]+=a0*bv.z;acc[0][3]+=a0*bv.w;
          acc[1][0]+=a1*bv.x;acc[1][1]+=a1*bv.y;acc[1][2]+=a1*bv.z;acc[1][3]+=a1*bv.w;
          acc[2][0]+=a2*bv.x;acc[2][1]+=a2*bv.y;acc[2][2]+=a2*bv.z;acc[2][3]+=a2*bv.w;
          acc[3][0]+=a3*bv.x;acc[3][1]+=a3*bv.y;acc[3][2]+=a3*bv.z;acc[3][3]+=a3*bv.w;
        }
        #pragma unroll
        for(int i=0;i<4;i++)
          #pragma unroll
          for(int j=0;j<4;j++) H2[(ty*4+i)*68+tx*4+j]=fmaxf(acc[i][j],0.f);
      }
      __syncthreads();
      { // phase C: F = relu(H2 @ W1_2 + b)
        float acc[4][4];
        #pragma unroll
        for(int i=0;i<4;i++)
          #pragma unroll
          for(int j=0;j<4;j++) acc[i][j]=BB[tx*4+j];
        #pragma unroll 4
        for(int k=0;k<64;k++){
          float a0=H2[(ty*4+0)*68+k],a1=H2[(ty*4+1)*68+k],a2=H2[(ty*4+2)*68+k],a3=H2[(ty*4+3)*68+k];
          float4 bv=*(const float4*)&WB[k*64+tx*4];
          acc[0][0]+=a0*bv.x;acc[0][1]+=a0*bv.y;acc[0][2]+=a0*bv.z;acc[0][3]+=a0*bv.w;
          acc[1][0]+=a1*bv.x;acc[1][1]+=a1*bv.y;acc[1][2]+=a1*bv.z;acc[1][3]+=a1*bv.w;
          acc[2][0]+=a2*bv.x;acc[2][1]+=a2*bv.y;acc[2][2]+=a2*bv.z;acc[2][3]+=a2*bv.w;
          acc[3][0]+=a3*bv.x;acc[3][1]+=a3*bv.y;acc[3][2]+=a3*bv.z;acc[3][3]+=a3*bv.w;
        }
        #pragma unroll
        for(int i=0;i<4;i++)
          #pragma unroll
          for(int j=0;j<4;j++) F[(ty*4+i)*68+tx*4+j]=fmaxf(acc[i][j],0.f);
      }
      __syncthreads();
      // phase D: online softmax over m
      if(t<64){
        float mx=-1e30f;
        #pragma unroll 8
        for(int c=0;c<64;c++) mx=fmaxf(mx,F[t*68+c]);
        RM[t]=mx;
      }
      __syncthreads();
      if(t==0){
        float tm=-1e30f;
        for(int mr=0;mr<64;mr++) tm=fmaxf(tm,RM[mr]);
        float oldM=MS[p], nM=fmaxf(oldM,tm);
        AL[0]=expf(oldM-nM); MS[p]=nM;
      }
      __syncthreads();
      float nM=MS[p], alpha=AL[0];
      if(t<64) EE[t]=expf(RM[t]-nM);
      __syncthreads();
      if(t<64){
        float acc=AS[p*64+t]*alpha;
        #pragma unroll 8
        for(int mr=0;mr<64;mr++) acc+=EE[mr]*F[mr*68+t];
        AS[p*64+t]=acc;
      } else if(t<67){
        int ch=t-64; float acc=CO[p*4+ch]*alpha; int mg=tile*64;
        for(int mr=0;mr<64;mr++) acc+=EE[mr]*g_rfi[(mg+mr)*3+ch];
        CO[p*4+ch]=acc;
      } else if(t==67){
        float z=ZS[p]*alpha;
        for(int mr=0;mr<64;mr++) z+=EE[mr];
        ZS[p]=z;
      }
      __syncthreads();
    }
  }
  for(int p=0;p<2;p++){
    if(t<64) g_att[(n0+p)*CC+t]=AS[p*64+t]/ZS[p];
    else if(t<67) g_corres[(n0+p)*3+t-64]=CO[p*4+t-64]/ZS[p];
  }
}

__global__ void head_kernel(const float* __restrict__ wm0,const float* __restrict__ bm0,
    const float* __restrict__ wm1,const float* __restrict__ bm1,
    const float* __restrict__ wm2,const float* __restrict__ bm2,float* __restrict__ outw){
  int n=blockIdx.x,t=threadIdx.x;
  __shared__ float a[64],h1[64],h2[128];
  if(t<64) a[t]=g_att[n*CC+t];
  __syncthreads();
  if(t<64){
    float s=bm0[t];
    #pragma unroll 4
    for(int k=0;k<64;k++) s+=a[k]*wm0[k*64+t];
    h1[t]=fmaxf(s,0.f);
  }
  __syncthreads();
  {
    float s=bm1[t];
    #pragma unroll 4
    for(int k=0;k<64;k++) s+=h1[k]*wm1[k*128+t];
    h2[t]=fmaxf(s,0.f);
  }
  __syncthreads();
  if(t==0){
    float l0=bm2[0],l1=bm2[1];
    for(int k=0;k<128;k++){l0+=h2[k]*wm2[k*2];l1+=h2[k]*wm2[k*2+1];}
    float mx=fmaxf(l0,l1),e0=expf(l0-mx),e1=expf(l1-mx),inv=1.f/(e0+e1);
    outw[n*2]=e0*inv; outw[n*2+1]=e1*inv;
    g_win[n]=(l1>l0)?1.f:0.f;
  }
}

__device__ float brs(float v,float* red){
  int t=threadIdx.x;
  red[t]=v; __syncthreads();
  for(int s=128;s>0;s>>=1){ if(t<s) red[t]+=red[t+s]; __syncthreads(); }
  float r=red[0]; __syncthreads();
  return r;
}

__global__ void pnp_kernel(float* __restrict__ out){
  __shared__ float red[256];
  int t=threadIdx.x;
  float w=g_win[t];
  float sx=g_xyz[t*3],sy=g_xyz[t*3+1],sz=g_xyz[t*3+2];
  float u=g_corres[t*3],v=g_corres[t*3+1];
  float dx=u*sz,dy=v*sz,dz=sz;
  float sw=brs(w,red);
  float wn=w/(sw+1e-8f);
  float scx=brs(wn*sx,red),scy=brs(wn*sy,red),scz=brs(wn*sz,red);
  float dcx=brs(wn*dx,red),dcy=brs(wn*dy,red),dcz=brs(wn*dz,red);
  float ax=sx-scx,ay=sy-scy,az=sz-scz;
  float bx=dx-dcx,by=dy-dcy,bz=dz-dcz;
  float hm[9];
  hm[0]=brs(wn*ax*bx,red);hm[1]=brs(wn*ax*by,red);hm[2]=brs(wn*ax*bz,red);
  hm[3]=brs(wn*ay*bx,red);hm[4]=brs(wn*ay*by,red);hm[5]=brs(wn*ay*bz,red);
  hm[6]=brs(wn*az*bx,red);hm[7]=brs(wn*az*by,red);hm[8]=brs(wn*az*bz,red);
  if(t==0){
    double h[3][3]={{hm[0],hm[1],hm[2]},{hm[3],hm[4],hm[5]},{hm[6],hm[7],hm[8]}};
    double A[3][3],V[3][3]={{1,0,0},{0,1,0},{0,0,1}};
    for(int i=0;i<3;i++)for(int j=0;j<3;j++){double s=0;for(int k=0;k<3;k++)s+=h[k][i]*h[k][j];A[i][j]=s;}
    const int P[3]={0,0,1},Q[3]={1,2,2};
    for(int sweep=0;sweep<20;sweep++)
      for(int r=0;r<3;r++){
        int p=P[r],qq=Q[r];
        double apq=A[p][qq];
        if(fabs(apq)<1e-300) continue;
        double tau=(A[qq][qq]-A[p][p])/(2.0*apq);
        double tt=((tau>=0)?1.0:-1.0)/(fabs(tau)+sqrt(1.0+tau*tau));
        double c=1.0/sqrt(1.0+tt*tt),s=tt*c;
        for(int k=0;k<3;k++){double a1=A[k][p],a2=A[k][qq];A[k][p]=c*a1-s*a2;A[k][qq]=s*a1+c*a2;}
        for(int k=0;k<3;k++){double a1=A[p][k],a2=A[qq][k];A[p][k]=c*a1-s*a2;A[qq][k]=s*a1+c*a2;}
        for(int k=0;k<3;k++){double v1=V[k][p],v2=V[k][qq];V[k][p]=c*v1-s*v2;V[k][qq]=s*v1+c*v2;}
      }
    double lam[3]={A[0][0],A[1][1],A[2][2]};
    int o[3]={0,1,2};
    if(lam[o[0]]<lam[o[1]]){int x=o[0];o[0]=o[1];o[1]=x;}
    if(lam[o[1]]<lam[o[2]]){int x=o[1];o[1]=o[2];o[2]=x;}
    if(lam[o[0]]<lam[o[1]]){int x=o[0];o[0]=o[1];o[1]=x;}
    double vv[3][3],uu[3][3],sg[3];
    for(int i=0;i<3;i++){
      sg[i]=sqrt(fmax(lam[o[i]],0.0));
      for(int k=0;k<3;k++) vv[i][k]=V[k][o[i]];
    }
    for(int i=0;i<2;i++){
      for(int j=0;j<3;j++){double s=0;for(int k=0;k<3;k++)s+=h[j][k]*vv[i][k];uu[i][j]=s/fmax(sg[i],1e-300);}
    }
    if(sg[2]>1e-9*sg[0]){
      for(int j=0;j<3;j++){double s=0;for(int k=0;k<3;k++)s+=h[j][k]*vv[2][k];uu[2][j]=s/sg[2];}
    } else {
      uu[2][0]=uu[0][1]*uu[1][2]-uu[0][2]*uu[1][1];
      uu[2][1]=uu[0][2]*uu[1][0]-uu[0][0]*uu[1][2];
      uu[2][2]=uu[0][0]*uu[1][1]-uu[0][1]*uu[1][0];
    }
    double detV=vv[0][0]*(vv[1][1]*vv[2][2]-vv[1][2]*vv[2][1])
               -vv[0][1]*(vv[1][0]*vv[2][2]-vv[1][2]*vv[2][0])
               +vv[0][2]*(vv[1][0]*vv[2][1]-vv[1][1]*vv[2][0]);
    double detU=uu[0][0]*(uu[1][1]*uu[2][2]-uu[1][2]*uu[2][1])
               -uu[0][1]*(uu[1][0]*uu[2][2]-uu[1][2]*uu[2][0])
               +uu[0][2]*(uu[1][0]*uu[2][1]-uu[1][1]*uu[2][0]);
    double d=detV*detU;
    double R[3][3];
    for(int i=0;i<3;i++)for(int j=0;j<3;j++)
      R[i][j]=vv[0][i]*uu[0][j]+vv[1][i]*uu[1][j]+d*vv[2][i]*uu[2][j];
    double sc[3]={scx,scy,scz},dc[3]={dcx,dcy,dcz};
    for(int i=0;i<3;i++){
      for(int j=0;j<3;j++) out[i*3+j]=(float)R[i][j];
      double s=0; for(int j=0;j<3;j++) s+=R[i][j]*sc[j];
      out[9+i]=(float)(dc[i]-s);
    }
  }
}

extern "C" void kernel_launch(void* const* d_in, const int* in_sizes, int n_in,
                              void* d_out, int out_size){
  const float* wx  =(const float*)d_in[0];
  const float* wp  =(const float*)d_in[1];
  const float* RF3 =(const float*)d_in[2];
  const float* RF3i=(const float*)d_in[3];
  const float* lz  =(const float*)d_in[4];
  const float* w2_0=(const float*)d_in[5];  const float* b2_0=(const float*)d_in[6];
  const float* w2_1=(const float*)d_in[7];  const float* b2_1=(const float*)d_in[8];
  const float* w2_2=(const float*)d_in[9];  const float* b2_2=(const float*)d_in[10];
  const float* w3_0=(const float*)d_in[11]; const float* b3_0=(const float*)d_in[12];
  const float* w3_1=(const float*)d_in[13]; const float* b3_1=(const float*)d_in[14];
  const float* w3_2=(const float*)d_in[15]; const float* b3_2=(const float*)d_in[16];
  const float* w1_0=(const float*)d_in[17]; const float* b1_0=(const float*)d_in[18];
  const float* w1_1=(const float*)d_in[19]; const float* b1_1=(const float*)d_in[20];
  const float* w1_2=(const float*)d_in[21]; const float* b1_2=(const float*)d_in[22];
  const float* wm_0=(const float*)d_in[23]; const float* bm_0=(const float*)d_in[24];
  const float* wm_1=(const float*)d_in[25]; const float* bm_1=(const float*)d_in[26];
  const float* wm_2=(const float*)d_in[27]; const float* bm_2=(const float*)d_in[28];
  float* out=(float*)d_out;

  cudaFuncSetAttribute(mlp2_kernel, cudaFuncAttributeMaxDynamicSharedMemorySize, MLP2_SMEM);
  cudaFuncSetAttribute(mlp3_kernel, cudaFuncAttributeMaxDynamicSharedMemorySize, MLP3_SMEM);
  cudaFuncSetAttribute(big_kernel,  cudaFuncAttributeMaxDynamicSharedMemorySize, BIG_SMEM);

  prep_kernel<<<MM,64>>>(wx,lz,RF3,RF3i);
  l2norm_kernel<<<NN,64>>>(wp,0);
  l2norm_kernel<<<MM,64>>>(nullptr,1);
  corr_kernel<<<dim3(MM/64,NN/64),256>>>(0);
  colmax_kernel<<<1,NN>>>(0);
  rowmax_kernel<<<MM/8,256>>>(0);
  knn_kernel<<<NN,256>>>();
  mlp2_kernel<<<NN,256,MLP2_SMEM>>>(wp,w2_0,b2_0,w2_1,b2_1,w2_2,b2_2);
  mlp3_kernel<<<MM,256,MLP3_SMEM>>>(w3_0,b3_0,w3_1,b3_1,w3_2,b3_2);
  l2norm_kernel<<<NN,64>>>(nullptr,2);
  l2norm_kernel<<<MM,64>>>(nullptr,3);
  corr_kernel<<<dim3(MM/64,NN/64),256>>>(1);
  colmax_kernel<<<1,NN>>>(1);
  rowmax_kernel<<<MM/8,256>>>(1);
  pack_kernel<<<NN,256>>>();
  basem_kernel<<<MM,128>>>(w1_0,b1_0);
  basen_kernel<<<NN,128>>>(wp,w1_0);
  big_kernel<<<NN/2,256,BIG_SMEM>>>(w1_0,w1_1,b1_1,w1_2,b1_2);
  head_kernel<<<NN,128>>>(wm_0,bm_0,wm_1,bm_1,wm_2,bm_2,out+12);
  pnp_kernel<<<1,NN>>>(out);
}

// round 6
// speedup vs baseline: 1.0264x; 1.0264x over previous
#include <cuda_runtime.h>
#include <math.h>

#define NN 256
#define MM 1024
#define CC 64
#define KK 16

__device__ float g_xyz[NN*3];
__device__ float g_rf[MM*CC];
__device__ float g_rfi[MM*3];
__device__ float g_wpn[NN*CC];
__device__ float g_rfn[MM*CC];
__device__ float g_sim1[MM*NN];
__device__ float g_sim2[MM*NN];
__device__ float g_invc1[NN], g_invr1[MM], g_invc2[NN], g_invr2[MM];
__device__ int   g_knn[NN*KK];
__device__ float g_pcf[NN*CC];
__device__ float g_imgf[MM*CC];
__device__ float g_pcn[NN*CC];
__device__ float g_imgn[MM*CC];
__device__ float4 g_simQ[NN*MM];
__device__ float g_basem[MM*128];
__device__ float g_basen[NN*128];
__device__ float g_att[NN*CC];
__device__ float g_corres[NN*3];
__device__ float g_win[NN];

__global__ void prep_kernel(const float* __restrict__ wx, const float* __restrict__ lz,
                            const float* __restrict__ RF3, const float* __restrict__ RF3i){
  int m=blockIdx.x, t=threadIdx.x;
  g_rf[m*CC+t]=RF3[t*MM+m];
  if(t<3) g_rfi[m*3+t]=RF3i[t*MM+m];
  if(m<NN&&t<3) g_xyz[m*3+t]=wx[m*3+t]*lz[m];
}

__global__ void l2norm_kernel(const float* __restrict__ ext,int sel){
  const float* src; float* dst;
  if(sel==0){src=ext;dst=g_wpn;} else if(sel==1){src=g_rf;dst=g_rfn;}
  else if(sel==2){src=g_pcf;dst=g_pcn;} else {src=g_imgf;dst=g_imgn;}
  int r=blockIdx.x,t=threadIdx.x;
  float v=src[r*CC+t], s=v*v;
  for(int o=16;o;o>>=1) s+=__shfl_down_sync(~0u,s,o);
  __shared__ float sh[2];
  if((t&31)==0) sh[t>>5]=s;
  __syncthreads();
  float n=fmaxf(sqrtf(sh[0]+sh[1]),1e-12f);
  dst[r*CC+t]=v/n;
}

__global__ __launch_bounds__(256) void corr_kernel(int sel){
  const float *A,*B; float* S;
  if(sel==0){A=g_rfn;B=g_wpn;S=g_sim1;} else {A=g_imgn;B=g_pcn;S=g_sim2;}
  __shared__ float As[64][65], Bs[64][65];
  int t=threadIdx.x, tx=t&15, ty=t>>4;
  int m0=blockIdx.x*64, n0=blockIdx.y*64;
  #pragma unroll
  for(int i=0;i<16;i++){int idx=t+i*256,r=idx>>6,c=idx&63;
    As[r][c]=A[(m0+r)*CC+c]; Bs[r][c]=B[(n0+r)*CC+c];}
  __syncthreads();
  float acc[4][4];
  #pragma unroll
  for(int i=0;i<4;i++)
    #pragma unroll
    for(int j=0;j<4;j++) acc[i][j]=0.f;
  #pragma unroll 8
  for(int k=0;k<64;k++){
    float a[4],b[4];
    #pragma unroll
    for(int i=0;i<4;i++){a[i]=As[ty*4+i][k]; b[i]=Bs[tx*4+i][k];}
    #pragma unroll
    for(int i=0;i<4;i++)
      #pragma unroll
      for(int j=0;j<4;j++) acc[i][j]+=a[i]*b[j];
  }
  #pragma unroll
  for(int i=0;i<4;i++)
    #pragma unroll
    for(int j=0;j<4;j++) S[(m0+ty*4+i)*NN+n0+tx*4+j]=acc[i][j];
}

// parallel column max (over m) per n
__global__ void colmax_kernel(int sel){
  const float* S=sel?g_sim2:g_sim1; float* ic=sel?g_invc2:g_invc1;
  int n=blockIdx.x, t=threadIdx.x;     // grid NN, block 128
  float mx=-1e30f;
  for(int m=t;m<MM;m+=128) mx=fmaxf(mx,S[m*NN+n]);
  for(int o=16;o;o>>=1) mx=fmaxf(mx,__shfl_down_sync(~0u,mx,o));
  __shared__ float sh[4];
  if((t&31)==0) sh[t>>5]=mx;
  __syncthreads();
  if(t==0){
    mx=fmaxf(fmaxf(sh[0],sh[1]),fmaxf(sh[2],sh[3]));
    ic[n]=1.f/(mx+1e-6f);
  }
}
__global__ void rowmax_kernel(int sel){
  const float* S=sel?g_sim2:g_sim1; float* ir=sel?g_invr2:g_invr1;
  int w=threadIdx.x>>5,l=threadIdx.x&31,m=blockIdx.x*8+w;
  float mx=-1e30f;
  for(int n=l;n<NN;n+=32) mx=fmaxf(mx,S[m*NN+n]);
  for(int o=16;o;o>>=1) mx=fmaxf(mx,__shfl_down_sync(~0u,mx,o));
  if(l==0) ir[m]=1.f/(mx+1e-10f);
}

__global__ void knn_kernel(){
  int n=blockIdx.x,t=threadIdx.x;
  __shared__ float sx[NN*3], d2[NN], wm[8];
  __shared__ int wi[8];
  for(int i=t;i<NN*3;i+=256) sx[i]=g_xyz[i];
  __syncthreads();
  float cx=sx[n*3],cy=sx[n*3+1],cz=sx[n*3+2];
  float dx=sx[t*3]-cx,dy=sx[t*3+1]-cy,dz=sx[t*3+2]-cz;
  d2[t]=dx*dx+dy*dy+dz*dz;
  __syncthreads();
  for(int it=0;it<KK;it++){
    float v=d2[t]; int id=t;
    for(int o=16;o;o>>=1){
      float ov=__shfl_down_sync(~0u,v,o); int oi=__shfl_down_sync(~0u,id,o);
      if(ov<v||(ov==v&&oi<id)){v=ov;id=oi;}
    }
    if((t&31)==0){wm[t>>5]=v;wi[t>>5]=id;}
    __syncthreads();
    if(t==0){
      float bv=wm[0];int bi=wi[0];
      for(int w=1;w<8;w++) if(wm[w]<bv||(wm[w]==bv&&wi[w]<bi)){bv=wm[w];bi=wi[w];}
      g_knn[n*KK+it]=bi; d2[bi]=1e38f;
    }
    __syncthreads();
  }
}

#define MLP2_SMEM (15888*4)
__global__ __launch_bounds__(256) void mlp2_kernel(const float* __restrict__ wp,
    const float* __restrict__ w0,const float* __restrict__ b0,
    const float* __restrict__ w1,const float* __restrict__ b1,
    const float* __restrict__ w2,const float* __restrict__ b2){
  extern __shared__ float sm[];
  float* W0=sm; float* W1=W0+4352; float* W2=W1+4096;
  float* B0=W2+4096; float* B1=B0+64; float* B2=B1+64;
  float* IN=B2+64; float* Ha=IN+1088; float* Hb=Ha+1024; float* wk=Hb+1024;
  int n=blockIdx.x,t=threadIdx.x;
  for(int i=t;i<4352;i+=256) W0[i]=w0[i];
  for(int i=t;i<4096;i+=256){W1[i]=w1[i];W2[i]=w2[i];}
  if(t<64){B0[t]=b0[t];B1[t]=b1[t];B2[t]=b2[t];}
  for(int i=t;i<16*68;i+=256){
    int k=i/68,f=i%68,nb=g_knn[n*KK+k]; float val;
    if(f<64) val=wp[nb*CC+f];
    else if(f<67) val=g_xyz[nb*3+(f-64)]-g_xyz[n*3+(f-64)];
    else{
      float dx=g_xyz[nb*3]-g_xyz[n*3],dy=g_xyz[nb*3+1]-g_xyz[n*3+1],dz=g_xyz[nb*3+2]-g_xyz[n*3+2];
      val=sqrtf(dx*dx+dy*dy+dz*dz);
    }
    IN[k*68+f]=val;
  }
  __syncthreads();
  for(int o=t;o<1024;o+=256){int k=o>>6,j=o&63; float s=B0[j];
    #pragma unroll 4
    for(int i=0;i<68;i++) s+=IN[k*68+i]*W0[i*64+j];
    Ha[o]=fmaxf(s,0.f);}
  __syncthreads();
  for(int o=t;o<1024;o+=256){int k=o>>6,j=o&63; float s=B1[j];
    #pragma unroll 4
    for(int i=0;i<64;i++) s+=Ha[k*64+i]*W1[i*64+j];
    Hb[o]=fmaxf(s,0.f);}
  __syncthreads();
  for(int o=t;o<1024;o+=256){int k=o>>6,j=o&63; float s=B2[j];
    #pragma unroll 4
    for(int i=0;i<64;i++) s+=Hb[k*64+i]*W2[i*64+j];
    Ha[o]=fmaxf(s,0.f);}
  __syncthreads();
  if(t<16){float mx=-1e30f; for(int j=0;j<64;j++) mx=fmaxf(mx,Ha[t*64+j]); wk[t]=mx;}
  __syncthreads();
  if(t==0){
    float mx=-1e30f; for(int k=0;k<16;k++) mx=fmaxf(mx,wk[k]);
    float s=0.f; for(int k=0;k<16;k++){wk[k]=expf(wk[k]-mx);s+=wk[k];}
    float inv=1.f/s; for(int k=0;k<16;k++) wk[k]*=inv;
  }
  __syncthreads();
  if(t<64){float s=0.f; for(int k=0;k<16;k++) s+=wk[k]*IN[k*68+t]; g_pcf[n*CC+t]=s;}
}

#define MLP3_SMEM (14443*4)
__global__ __launch_bounds__(256) void mlp3_kernel(
    const float* __restrict__ w0,const float* __restrict__ b0,
    const float* __restrict__ w1,const float* __restrict__ b1,
    const float* __restrict__ w2,const float* __restrict__ b2){
  extern __shared__ float sm[];
  float* W0=sm; float* W1=W0+4288; float* W2=W1+4096;
  float* B0=W2+4096; float* B1=B0+64; float* B2=B1+64;
  float* IN=B2+64; float* Ha=IN+603; float* Hb=Ha+576; float* wk=Hb+576;
  int m=blockIdx.x,t=threadIdx.x,y=m>>5,x=m&31;
  for(int i=t;i<4288;i+=256) W0[i]=w0[i];
  for(int i=t;i<4096;i+=256){W1[i]=w1[i];W2[i]=w2[i];}
  if(t<64){B0[t]=b0[t];B1[t]=b1[t];B2[t]=b2[t];}
  for(int i=t;i<9*67;i+=256){
    int k=i/67,f=i%67,dy=k/3-1,dx=k%3-1,yy=y+dy,xx=x+dx;
    float val=0.f;
    if(yy>=0&&yy<32&&xx>=0&&xx<32){int mm=yy*32+xx; val=(f<3)?g_rfi[mm*3+f]:g_rf[mm*CC+f-3];}
    IN[k*67+f]=val;
  }
  __syncthreads();
  for(int o=t;o<576;o+=256){int k=o>>6,j=o&63; float s=B0[j];
    #pragma unroll 4
    for(int i=0;i<67;i++) s+=IN[k*67+i]*W0[i*64+j];
    Ha[o]=fmaxf(s,0.f);}
  __syncthreads();
  for(int o=t;o<576;o+=256){int k=o>>6,j=o&63; float s=B1[j];
    #pragma unroll 4
    for(int i=0;i<64;i++) s+=Ha[k*64+i]*W1[i*64+j];
    Hb[o]=fmaxf(s,0.f);}
  __syncthreads();
  for(int o=t;o<576;o+=256){int k=o>>6,j=o&63; float s=B2[j];
    #pragma unroll 4
    for(int i=0;i<64;i++) s+=Hb[k*64+i]*W2[i*64+j];
    Ha[o]=fmaxf(s,0.f);}
  __syncthreads();
  if(t<9){float mx=-1e30f; for(int j=0;j<64;j++) mx=fmaxf(mx,Ha[t*64+j]); wk[t]=mx;}
  __syncthreads();
  if(t==0){
    float mx=-1e30f; for(int k=0;k<9;k++) mx=fmaxf(mx,wk[k]);
    float s=0.f; for(int k=0;k<9;k++){wk[k]=expf(wk[k]-mx);s+=wk[k];}
    float inv=1.f/s; for(int k=0;k<9;k++) wk[k]*=inv;
  }
  __syncthreads();
  if(t<64){float s=0.f; for(int k=0;k<9;k++) s+=wk[k]*IN[k*67+3+t]; g_imgf[m*CC+t]=s;}
}

// coalesced-read pack: grid MM, block NN
__global__ void pack_kernel(){
  int m=blockIdx.x, n=threadIdx.x;
  float s1=g_sim1[m*NN+n], s2=g_sim2[m*NN+n];
  float4 q; q.x=s1*g_invc1[n]; q.y=s1*g_invr1[m]; q.z=s2*g_invc2[n]; q.w=s2*g_invr2[m];
  g_simQ[n*MM+m]=q;
}

__global__ void basem_kernel(const float* __restrict__ w1_0,const float* __restrict__ b1_0){
  int m=blockIdx.x,t=threadIdx.x;
  __shared__ float in[67];
  if(t<3) in[t]=g_rfi[m*3+t]; else if(t<67) in[t]=g_rf[m*CC+t-3];
  __syncthreads();
  float acc=b1_0[t];
  #pragma unroll
  for(int i=0;i<3;i++) acc+=in[i]*w1_0[(3+i)*128+t];
  #pragma unroll 4
  for(int i=0;i<64;i++) acc+=in[3+i]*w1_0[(70+i)*128+t];
  g_basem[m*128+t]=acc;
}
__global__ void basen_kernel(const float* __restrict__ wp,const float* __restrict__ w1_0){
  int n=blockIdx.x,t=threadIdx.x;
  __shared__ float in[67];
  if(t<3) in[t]=g_xyz[n*3+t]; else if(t<67) in[t]=wp[n*CC+t-3];
  __syncthreads();
  float acc=0.f;
  #pragma unroll
  for(int i=0;i<3;i++) acc+=in[i]*w1_0[i*128+t];
  #pragma unroll 4
  for(int i=0;i<64;i++) acc+=in[3+i]*w1_0[(6+i)*128+t];
  g_basen[n*128+t]=acc;
}

// ------------------- big fused kernel: 512 threads, f32x2 GEMMs -------------------
#define OWS 0
#define OWA 512
#define OWB 8704
#define OBA 12800
#define OBB 12864
#define OBN 12928
#define OBM 13184
#define OH1 21440
#define OH2 29696
#define OF  34048
#define ORM 38400
#define OEE 38464
#define OSC 38528
#define OAS 38784
#define OCO 38912
#define OZS 38920
#define OMS 38922
#define OAL 38924
#define BIG_SMEM (38928*4)

#define PACK2(d,x) asm("mov.b64 %0,{%1,%1};":"=l"(d):"r"(__float_as_uint(x)))
#define FMA2(d,a,b) asm("fma.rn.f32x2 %0,%1,%2,%0;":"+l"(d):"l"(a),"l"(b))
#define UNPK(a,d0,d1) { unsigned int _lo,_hi; asm("mov.b64 {%0,%1},%2;":"=r"(_lo),"=r"(_hi):"l"(a)); d0=__uint_as_float(_lo); d1=__uint_as_float(_hi); }

__global__ __launch_bounds__(512,1) void big_kernel(
    const float* __restrict__ w1_0,const float* __restrict__ w1_1,const float* __restrict__ b1_1,
    const float* __restrict__ w1_2,const float* __restrict__ b1_2){
  extern __shared__ float sm[];
  float* WS=sm+OWS; float* WA=sm+OWA; float* WB=sm+OWB;
  float* BA=sm+OBA; float* BB=sm+OBB; float* BN=sm+OBN; float* Bm=sm+OBM;
  float* H1=sm+OH1; float* H2=sm+OH2; float* F=sm+OF;
  float* RM=sm+ORM; float* EE=sm+OEE; float* SC=sm+OSC; float* AS=sm+OAS;
  float* CO=sm+OCO; float* ZS=sm+OZS; float* MS=sm+OMS; float* AL=sm+OAL;
  int t=threadIdx.x, n0=blockIdx.x*2;
  if(t<512) WS[t]=w1_0[134*128+t];
  for(int i=t;i<8192;i+=512) WA[i]=w1_1[i];
  for(int i=t;i<4096;i+=512) WB[i]=w1_2[i];
  if(t<64){BA[t]=b1_1[t];BB[t]=b1_2[t];}
  if(t<256) BN[t]=g_basen[n0*128+t];
  if(t<128) AS[t]=0.f;
  if(t<8) CO[t]=0.f;
  if(t==0){ZS[0]=ZS[1]=0.f; MS[0]=MS[1]=-1e30f;}
  __syncthreads();
  int tx=t&15, ty=t>>4;          // ty 0..31 : rows ty*2, ty*2+1 ; cols tx*4..+3
  int mloc=t&63, q=t>>6;         // phase A: 8 groups of 16 channels
  for(int tile=0;tile<16;tile++){
    for(int idx=t;idx<64*128;idx+=512){int mr=idx>>7,c=idx&127; Bm[mr*129+c]=g_basem[(tile*64+mr)*128+c];}
    __syncthreads();
    for(int p=0;p<2;p++){
      int n=n0+p;
      { // phase A: H1 = relu(basen + basem + sim4 @ WS)
        float4 s4=g_simQ[n*MM+tile*64+mloc];
        const float* bn=BN+p*128;
        #pragma unroll
        for(int i=0;i<16;i++){
          int c=q*16+i;
          float h=bn[c]+Bm[mloc*129+c]+s4.x*WS[c]+s4.y*WS[128+c]+s4.z*WS[256+c]+s4.w*WS[384+c];
          H1[mloc*129+c]=fmaxf(h,0.f);
        }
      }
      __syncthreads();
      { // phase B: H2 = relu(H1 @ W1_1 + b)  64x128 @ 128x64, f32x2
        unsigned long long a00,a01,a10,a11;
        a00=*(const unsigned long long*)&BA[tx*4];
        a01=*(const unsigned long long*)&BA[tx*4+2];
        a10=a00; a11=a01;
        int r0=ty*2;
        #pragma unroll 4
        for(int k=0;k<128;k++){
          float v0=H1[r0*129+k], v1=H1[(r0+1)*129+k];
          unsigned long long p0,p1,w01,w23;
          PACK2(p0,v0); PACK2(p1,v1);
          w01=*(const unsigned long long*)&WA[k*64+tx*4];
          w23=*(const unsigned long long*)&WA[k*64+tx*4+2];
          FMA2(a00,p0,w01); FMA2(a01,p0,w23);
          FMA2(a10,p1,w01); FMA2(a11,p1,w23);
        }
        float x0,x1;
        UNPK(a00,x0,x1); H2[r0*68+tx*4+0]=fmaxf(x0,0.f); H2[r0*68+tx*4+1]=fmaxf(x1,0.f);
        UNPK(a01,x0,x1); H2[r0*68+tx*4+2]=fmaxf(x0,0.f); H2[r0*68+tx*4+3]=fmaxf(x1,0.f);
        UNPK(a10,x0,x1); H2[(r0+1)*68+tx*4+0]=fmaxf(x0,0.f); H2[(r0+1)*68+tx*4+1]=fmaxf(x1,0.f);
        UNPK(a11,x0,x1); H2[(r0+1)*68+tx*4+2]=fmaxf(x0,0.f); H2[(r0+1)*68+tx*4+3]=fmaxf(x1,0.f);
      }
      __syncthreads();
      { // phase C: F = relu(H2 @ W1_2 + b)  64x64 @ 64x64, f32x2
        unsigned long long a00,a01,a10,a11;
        a00=*(const unsigned long long*)&BB[tx*4];
        a01=*(const unsigned long long*)&BB[tx*4+2];
        a10=a00; a11=a01;
        int r0=ty*2;
        #pragma unroll 4
        for(int k=0;k<64;k++){
          float v0=H2[r0*68+k], v1=H2[(r0+1)*68+k];
          unsigned long long p0,p1,w01,w23;
          PACK2(p0,v0); PACK2(p1,v1);
          w01=*(const unsigned long long*)&WB[k*64+tx*4];
          w23=*(const unsigned long long*)&WB[k*64+tx*4+2];
          FMA2(a00,p0,w01); FMA2(a01,p0,w23);
          FMA2(a10,p1,w01); FMA2(a11,p1,w23);
        }
        float x0,x1;
        UNPK(a00,x0,x1); F[r0*68+tx*4+0]=fmaxf(x0,0.f); F[r0*68+tx*4+1]=fmaxf(x1,0.f);
        UNPK(a01,x0,x1); F[r0*68+tx*4+2]=fmaxf(x0,0.f); F[r0*68+tx*4+3]=fmaxf(x1,0.f);
        UNPK(a10,x0,x1); F[(r0+1)*68+tx*4+0]=fmaxf(x0,0.f); F[(r0+1)*68+tx*4+1]=fmaxf(x1,0.f);
        UNPK(a11,x0,x1); F[(r0+1)*68+tx*4+2]=fmaxf(x0,0.f); F[(r0+1)*68+tx*4+3]=fmaxf(x1,0.f);
      }
      __syncthreads();
      // ---- phase D: online softmax over m (parallel reductions) ----
      if(t<256){ int r=t&63,g=t>>6; float mx=-1e30f;
        #pragma unroll
        for(int c=g*16;c<g*16+16;c++) mx=fmaxf(mx,F[r*68+c]);
        SC[g*64+r]=mx; }
      __syncthreads();
      if(t<64) RM[t]=fmaxf(fmaxf(SC[t],SC[64+t]),fmaxf(SC[128+t],SC[192+t]));
      __syncthreads();
      if(t<32){
        float v=fmaxf(RM[t],RM[t+32]);
        for(int o=16;o;o>>=1) v=fmaxf(v,__shfl_down_sync(~0u,v,o));
        if(t==0){ float oldM=MS[p], nM=fmaxf(oldM,v); AL[0]=expf(oldM-nM); MS[p]=nM; }
      }
      __syncthreads();
      if(t<64) EE[t]=expf(RM[t]-MS[p]);
      __syncthreads();
      float alpha=AL[0];
      if(t<256){ int c=t&63,g=t>>6; float s=0.f;
        #pragma unroll
        for(int r=g*16;r<g*16+16;r++) s+=EE[r]*F[r*68+c];
        SC[g*64+c]=s; }
      else if(t>=448&&t<451){ int ch=t-448; float acc=CO[p*4+ch]*alpha; int mg=tile*64;
        for(int r=0;r<64;r++) acc+=EE[r]*g_rfi[(mg+r)*3+ch];
        CO[p*4+ch]=acc; }
      else if(t==451){ float z=ZS[p]*alpha;
        for(int r=0;r<64;r++) z+=EE[r];
        ZS[p]=z; }
      __syncthreads();
      if(t<64) AS[p*64+t]=AS[p*64+t]*alpha + SC[t]+SC[64+t]+SC[128+t]+SC[192+t];
      __syncthreads();
    }
  }
  for(int p=0;p<2;p++){
    if(t<64) g_att[(n0+p)*CC+t]=AS[p*64+t]/ZS[p];
    else if(t<67) g_corres[(n0+p)*3+t-64]=CO[p*4+t-64]/ZS[p];
  }
}

__global__ void head_kernel(const float* __restrict__ wm0,const float* __restrict__ bm0,
    const float* __restrict__ wm1,const float* __restrict__ bm1,
    const float* __restrict__ wm2,const float* __restrict__ bm2,float* __restrict__ outw){
  int n=blockIdx.x,t=threadIdx.x;
  __shared__ float a[64],h1[64],h2[128];
  if(t<64) a[t]=g_att[n*CC+t];
  __syncthreads();
  if(t<64){
    float s=bm0[t];
    #pragma unroll 4
    for(int k=0;k<64;k++) s+=a[k]*wm0[k*64+t];
    h1[t]=fmaxf(s,0.f);
  }
  __syncthreads();
  {
    float s=bm1[t];
    #pragma unroll 4
    for(int k=0;k<64;k++) s+=h1[k]*wm1[k*128+t];
    h2[t]=fmaxf(s,0.f);
  }
  __syncthreads();
  if(t==0){
    float l0=bm2[0],l1=bm2[1];
    for(int k=0;k<128;k++){l0+=h2[k]*wm2[k*2];l1+=h2[k]*wm2[k*2+1];}
    float mx=fmaxf(l0,l1),e0=expf(l0-mx),e1=expf(l1-mx),inv=1.f/(e0+e1);
    outw[n*2]=e0*inv; outw[n*2+1]=e1*inv;
    g_win[n]=(l1>l0)?1.f:0.f;
  }
}

__device__ float brs(float v,float* red){
  int t=threadIdx.x;
  red[t]=v; __syncthreads();
  for(int s=128;s>0;s>>=1){ if(t<s) red[t]+=red[t+s]; __syncthreads(); }
  float r=red[0]; __syncthreads();
  return r;
}

__global__ void pnp_kernel(float* __restrict__ out){
  __shared__ float red[256];
  int t=threadIdx.x;
  float w=g_win[t];
  float sx=g_xyz[t*3],sy=g_xyz[t*3+1],sz=g_xyz[t*3+2];
  float u=g_corres[t*3],v=g_corres[t*3+1];
  float dx=u*sz,dy=v*sz,dz=sz;
  float sw=brs(w,red);
  float wn=w/(sw+1e-8f);
  float scx=brs(wn*sx,red),scy=brs(wn*sy,red),scz=brs(wn*sz,red);
  float dcx=brs(wn*dx,red),dcy=brs(wn*dy,red),dcz=brs(wn*dz,red);
  float ax=sx-scx,ay=sy-scy,az=sz-scz;
  float bx=dx-dcx,by=dy-dcy,bz=dz-dcz;
  float hm[9];
  hm[0]=brs(wn*ax*bx,red);hm[1]=brs(wn*ax*by,red);hm[2]=brs(wn*ax*bz,red);
  hm[3]=brs(wn*ay*bx,red);hm[4]=brs(wn*ay*by,red);hm[5]=brs(wn*ay*bz,red);
  hm[6]=brs(wn*az*bx,red);hm[7]=brs(wn*az*by,red);hm[8]=brs(wn*az*bz,red);
  if(t==0){
    double h[3][3]={{hm[0],hm[1],hm[2]},{hm[3],hm[4],hm[5]},{hm[6],hm[7],hm[8]}};
    double A[3][3],V[3][3]={{1,0,0},{0,1,0},{0,0,1}};
    for(int i=0;i<3;i++)for(int j=0;j<3;j++){double s=0;for(int k=0;k<3;k++)s+=h[k][i]*h[k][j];A[i][j]=s;}
    const int P[3]={0,0,1},Q[3]={1,2,2};
    for(int sweep=0;sweep<20;sweep++)
      for(int r=0;r<3;r++){
        int p=P[r],qq=Q[r];
        double apq=A[p][qq];
        if(fabs(apq)<1e-300) continue;
        double tau=(A[qq][qq]-A[p][p])/(2.0*apq);
        double tt=((tau>=0)?1.0:-1.0)/(fabs(tau)+sqrt(1.0+tau*tau));
        double c=1.0/sqrt(1.0+tt*tt),s=tt*c;
        for(int k=0;k<3;k++){double a1=A[k][p],a2=A[k][qq];A[k][p]=c*a1-s*a2;A[k][qq]=s*a1+c*a2;}
        for(int k=0;k<3;k++){double a1=A[p][k],a2=A[qq][k];A[p][k]=c*a1-s*a2;A[qq][k]=s*a1+c*a2;}
        for(int k=0;k<3;k++){double v1=V[k][p],v2=V[k][qq];V[k][p]=c*v1-s*v2;V[k][qq]=s*v1+c*v2;}
      }
    double lam[3]={A[0][0],A[1][1],A[2][2]};
    int o[3]={0,1,2};
    if(lam[o[0]]<lam[o[1]]){int x=o[0];o[0]=o[1];o[1]=x;}
    if(lam[o[1]]<lam[o[2]]){int x=o[1];o[1]=o[2];o[2]=x;}
    if(lam[o[0]]<lam[o[1]]){int x=o[0];o[0]=o[1];o[1]=x;}
    double vv[3][3],uu[3][3],sg[3];
    for(int i=0;i<3;i++){
      sg[i]=sqrt(fmax(lam[o[i]],0.0));
      for(int k=0;k<3;k++) vv[i][k]=V[k][o[i]];
    }
    for(int i=0;i<2;i++){
      for(int j=0;j<3;j++){double s=0;for(int k=0;k<3;k++)s+=h[j][k]*vv[i][k];uu[i][j]=s/fmax(sg[i],1e-300);}
    }
    if(sg[2]>1e-9*sg[0]){
      for(int j=0;j<3;j++){double s=0;for(int k=0;k<3;k++)s+=h[j][k]*vv[2][k];uu[2][j]=s/sg[2];}
    } else {
      uu[2][0]=uu[0][1]*uu[1][2]-uu[0][2]*uu[1][1];
      uu[2][1]=uu[0][2]*uu[1][0]-uu[0][0]*uu[1][2];
      uu[2][2]=uu[0][0]*uu[1][1]-uu[0][1]*uu[1][0];
    }
    double detV=vv[0][0]*(vv[1][1]*vv[2][2]-vv[1][2]*vv[2][1])
               -vv[0][1]*(vv[1][0]*vv[2][2]-vv[1][2]*vv[2][0])
               +vv[0][2]*(vv[1][0]*vv[2][1]-vv[1][1]*vv[2][0]);
    double detU=uu[0][0]*(uu[1][1]*uu[2][2]-uu[1][2]*uu[2][1])
               -uu[0][1]*(uu[1][0]*uu[2][2]-uu[1][2]*uu[2][0])
               +uu[0][2]*(uu[1][0]*uu[2][1]-uu[1][1]*uu[2][0]);
    double d=detV*detU;
    double R[3][3];
    for(int i=0;i<3;i++)for(int j=0;j<3;j++)
      R[i][j]=vv[0][i]*uu[0][j]+vv[1][i]*uu[1][j]+d*vv[2][i]*uu[2][j];
    double sc[3]={scx,scy,scz},dc[3]={dcx,dcy,dcz};
    for(int i=0;i<3;i++){
      for(int j=0;j<3;j++) out[i*3+j]=(float)R[i][j];
      double s=0; for(int j=0;j<3;j++) s+=R[i][j]*sc[j];
      out[9+i]=(float)(dc[i]-s);
    }
  }
}

extern "C" void kernel_launch(void* const* d_in, const int* in_sizes, int n_in,
                              void* d_out, int out_size){
  const float* wx  =(const float*)d_in[0];
  const float* wp  =(const float*)d_in[1];
  const float* RF3 =(const float*)d_in[2];
  const float* RF3i=(const float*)d_in[3];
  const float* lz  =(const float*)d_in[4];
  const float* w2_0=(const float*)d_in[5];  const float* b2_0=(const float*)d_in[6];
  const float* w2_1=(const float*)d_in[7];  const float* b2_1=(const float*)d_in[8];
  const float* w2_2=(const float*)d_in[9];  const float* b2_2=(const float*)d_in[10];
  const float* w3_0=(const float*)d_in[11]; const float* b3_0=(const float*)d_in[12];
  const float* w3_1=(const float*)d_in[13]; const float* b3_1=(const float*)d_in[14];
  const float* w3_2=(const float*)d_in[15]; const float* b3_2=(const float*)d_in[16];
  const float* w1_0=(const float*)d_in[17]; const float* b1_0=(const float*)d_in[18];
  const float* w1_1=(const float*)d_in[19]; const float* b1_1=(const float*)d_in[20];
  const float* w1_2=(const float*)d_in[21]; const float* b1_2=(const float*)d_in[22];
  const float* wm_0=(const float*)d_in[23]; const float* bm_0=(const float*)d_in[24];
  const float* wm_1=(const float*)d_in[25]; const float* bm_1=(const float*)d_in[26];
  const float* wm_2=(const float*)d_in[27]; const float* bm_2=(const float*)d_in[28];
  float* out=(float*)d_out;

  cudaFuncSetAttribute(mlp2_kernel, cudaFuncAttributeMaxDynamicSharedMemorySize, MLP2_SMEM);
  cudaFuncSetAttribute(mlp3_kernel, cudaFuncAttributeMaxDynamicSharedMemorySize, MLP3_SMEM);
  cudaFuncSetAttribute(big_kernel,  cudaFuncAttributeMaxDynamicSharedMemorySize, BIG_SMEM);

  prep_kernel<<<MM,64>>>(wx,lz,RF3,RF3i);
  l2norm_kernel<<<NN,64>>>(wp,0);
  l2norm_kernel<<<MM,64>>>(nullptr,1);
  corr_kernel<<<dim3(MM/64,NN/64),256>>>(0);
  colmax_kernel<<<NN,128>>>(0);
  rowmax_kernel<<<MM/8,256>>>(0);
  knn_kernel<<<NN,256>>>();
  mlp2_kernel<<<NN,256,MLP2_SMEM>>>(wp,w2_0,b2_0,w2_1,b2_1,w2_2,b2_2);
  mlp3_kernel<<<MM,256,MLP3_SMEM>>>(w3_0,b3_0,w3_1,b3_1,w3_2,b3_2);
  l2norm_kernel<<<NN,64>>>(nullptr,2);
  l2norm_kernel<<<MM,64>>>(nullptr,3);
  corr_kernel<<<dim3(MM/64,NN/64),256>>>(1);
  colmax_kernel<<<NN,128>>>(1);
  rowmax_kernel<<<MM/8,256>>>(1);
  pack_kernel<<<MM,NN>>>();
  basem_kernel<<<MM,128>>>(w1_0,b1_0);
  basen_kernel<<<NN,128>>>(wp,w1_0);
  big_kernel<<<NN/2,512,BIG_SMEM>>>(w1_0,w1_1,b1_1,w1_2,b1_2);
  head_kernel<<<NN,128>>>(wm_0,bm_0,wm_1,bm_1,wm_2,bm_2,out+12);
  pnp_kernel<<<1,NN>>>(out);
}